// round 17
// baseline (speedup 1.0000x reference)
#include <cuda_runtime.h>
#include <math_constants.h>

#define NTOK 1024
#define DIM 128
#define TI 8            // rows per block (attn)
#define TJ 64           // j-tile
#define NT 1024         // threads, attn (32 warps)
#define KP 132          // K/V smem pitch
#define NTILE (NTOK / TJ)
#define LOG2E 1.4426950408889634f

typedef unsigned long long ull;

// packed f32x2 helpers (sm_100+/sm_103a)
__device__ __forceinline__ ull ADD2(ull a, ull b) {
    ull r; asm("add.rn.f32x2 %0, %1, %2;" : "=l"(r) : "l"(a), "l"(b)); return r;
}
__device__ __forceinline__ ull FMA2(ull a, ull b, ull c) {
    ull r; asm("fma.rn.f32x2 %0, %1, %2, %3;" : "=l"(r) : "l"(a), "l"(b), "l"(c)); return r;
}
// packed relu via scalar FMNMX pair (no packed f32 max; FMNMX = alu pipe)
__device__ __forceinline__ ull RELU2(ull a) {
    float lo, hi;
    asm("mov.b64 {%0, %1}, %2;" : "=f"(lo), "=f"(hi) : "l"(a));
    lo = fmaxf(lo, 0.f); hi = fmaxf(hi, 0.f);
    ull r; asm("mov.b64 %0, {%1, %2};" : "=l"(r) : "f"(lo), "f"(hi)); return r;
}
__device__ __forceinline__ float HSUM2(ull a) {
    float lo, hi;
    asm("mov.b64 {%0, %1}, %2;" : "=f"(lo), "=f"(hi) : "l"(a));
    return lo + hi;
}
// cp.async 16B
__device__ __forceinline__ void cpa16(unsigned dst, const void* src) {
    asm volatile("cp.async.cg.shared.global [%0], [%1], 16;" :: "r"(dst), "l"(src));
}
#define CP_COMMIT() asm volatile("cp.async.commit_group;" ::: "memory")
#define CP_WAIT0()  asm volatile("cp.async.wait_group 0;" ::: "memory")

// scratch for Q,K,V (static device arrays — no allocation)
__device__ float g_Q[NTOK * DIM];
__device__ float g_K[NTOK * DIM];
__device__ float g_V[NTOK * DIM];

// ---------------------------------------------------------------------------
// Kernel 1: Q,K,V = x @ W + b.  128 blocks x 384 threads.
// ---------------------------------------------------------------------------
__global__ __launch_bounds__(384) void qkv_kernel(
    const float* __restrict__ x,
    const float* __restrict__ WQ, const float* __restrict__ bQ,
    const float* __restrict__ WK, const float* __restrict__ bK,
    const float* __restrict__ WV, const float* __restrict__ bV)
{
    __shared__ float xs[8 * DIM];
    const int tid = threadIdx.x;
    const int i0 = blockIdx.x * 8;

    for (int idx = tid; idx < 8 * DIM; idx += 384)
        xs[idx] = x[i0 * DIM + idx];
    __syncthreads();

    const int d   = tid & 127;
    const int mat = tid >> 7;   // 0=Q 1=K 2=V
    const float* W = (mat == 0) ? WQ : (mat == 1) ? WK : WV;
    const float* b = (mat == 0) ? bQ : (mat == 1) ? bK : bV;
    float* outp    = (mat == 0) ? g_Q : (mat == 1) ? g_K : g_V;

    float acc[8];
    const float bv = b[d];
#pragma unroll
    for (int r = 0; r < 8; r++) acc[r] = bv;

#pragma unroll 4
    for (int k = 0; k < DIM; k += 4) {
        const float w0 = W[(k + 0) * DIM + d];
        const float w1 = W[(k + 1) * DIM + d];
        const float w2 = W[(k + 2) * DIM + d];
        const float w3 = W[(k + 3) * DIM + d];
#pragma unroll
        for (int r = 0; r < 8; r++) {
            const float4 xq = *(const float4*)&xs[r * DIM + k];
            acc[r] = fmaf(xq.x, w0, fmaf(xq.y, w1, fmaf(xq.z, w2, fmaf(xq.w, w3, acc[r]))));
        }
    }
#pragma unroll
    for (int r = 0; r < 8; r++)
        outp[(i0 + r) * DIM + d] = acc[r];
}

// ---------------------------------------------------------------------------
// Kernel 2: fused pass, TI=8, 1024 threads (32 warps = 8/SMSP), 1 CTA/SM,
// grid 128. K,V double-buffered cp.async, 2 barriers/tile, <=64 regs/thread.
//   phase-e (round-15 layout): warp w: rh_e=w>>4, je=(w&15)*4+(lane&3),
//            g=lane>>2 in [0,8); 4 E_ITs over 1/8 of d; 3-round reduce-scatter;
//            lanes<16 own row (rh_e*4 + (g&3)) at column je; 1 exp2/thread.
//   accumulate (round-14 reuse profile): thread (dp=tid&63, jq=(tid>>6)&7,
//            rh=tid>>9): rows rh*4..+3, 8 j's; 8 packed accumulators.
//            Total K/V LDS count identical to round 14 (no re-read scaling).
// smem ~144KB.
// ---------------------------------------------------------------------------
__global__ __launch_bounds__(NT, 1) void attn_kernel(
    const float* __restrict__ wA,
    const float* __restrict__ W_Ev,
    const float* __restrict__ b_Ev,
    float* __restrict__ out)
{
    extern __shared__ float sm[];
    float* Kb0  = sm;              // [TJ][KP] = 8448
    float* Kb1  = sm + 8448;
    float* Vb0  = sm + 16896;
    float* Vb1  = sm + 25344;
    float* Qe   = sm + 33792;      // [8][DIM] = 1024
    float* wAs  = sm + 34816;      // [DIM] = 128
    float* p16d = sm + 34944;      // [TJ][16] duplicated p = 1024
    float* l_ws = sm + 35968;      // [32][4] = 128
    // total 36096 floats = 144384 B

    const int tid  = threadIdx.x;
    const int lane = tid & 31;
    const int warp = tid >> 5;
    const int i0   = blockIdx.x * TI;
    // phase-e ids
    const int rh_e = warp >> 4;               // row half 0/1
    const int je   = ((warp & 15) << 2) + (lane & 3);
    const int g    = lane >> 2;               // d-chunk in [0,8)
    // accumulate ids
    const int dp   = tid & 63;                // d-pair
    const int jq   = (tid >> 6) & 7;          // j-eighth
    const int rh   = tid >> 9;                // row half 0/1

    // per-thread tile slots: float4 idx = it*NT + tid (2 slots)
    unsigned koff[2];
#pragma unroll
    for (int it = 0; it < 2; it++) {
        const int idx = it * NT + tid;
        koff[it] = (unsigned)(((idx >> 5) * KP + (idx & 31) * 4) * 4);
    }
    const unsigned kb0 = (unsigned)__cvta_generic_to_shared(Kb0);
    const unsigned kb1 = (unsigned)__cvta_generic_to_shared(Kb1);
    const unsigned vb0 = (unsigned)__cvta_generic_to_shared(Vb0);
    const unsigned vb1 = (unsigned)__cvta_generic_to_shared(Vb1);

    // init Q table (row-major, 8 rows) + wA
    if (tid < TI * DIM) {
        const int r = tid >> 7, dd = tid & 127;
        Qe[tid] = g_Q[(i0 + r) * DIM + dd];
    }
    if (tid < DIM) wAs[tid] = wA[tid];

    // accumulate-phase Q d-pairs (rows rh*4..rh*4+3)
    const ull q0p = *(const ull*)&g_Q[(i0 + rh * 4 + 0) * DIM + 2 * dp];
    const ull q1p = *(const ull*)&g_Q[(i0 + rh * 4 + 1) * DIM + 2 * dp];
    const ull q2p = *(const ull*)&g_Q[(i0 + rh * 4 + 2) * DIM + 2 * dp];
    const ull q3p = *(const ull*)&g_Q[(i0 + rh * 4 + 3) * DIM + 2 * dp];

    ull af0 = 0ull, af1 = 0ull, af2 = 0ull, af3 = 0ull;
    ull av0 = 0ull, av1 = 0ull, av2 = 0ull, av3 = 0ull;
    float l_acc = 0.f;

    // prologue: async-load K(0), V(0) into buf0
    {
        const float4* Kg = (const float4*)(g_K);
        const float4* Vg = (const float4*)(g_V);
#pragma unroll
        for (int it = 0; it < 2; it++) {
            cpa16(kb0 + koff[it], &Kg[it * NT + tid]);
            cpa16(vb0 + koff[it], &Vg[it * NT + tid]);
        }
        CP_COMMIT();
    }

    for (int ti = 0; ti < NTILE; ti++) {
        const float* Kcur = (ti & 1) ? Kb1 : Kb0;
        const float* Vcur = (ti & 1) ? Vb1 : Vb0;

        CP_WAIT0();        // K(ti), V(ti) landed
        __syncthreads();   // visible; prev accumulate done (covers Qe/wAs ti=0)

        // ---- phase e/p: e over d-chunk g for 4 rows (half rh_e) at column je
        {
            ull e0 = 0ull, e1 = 0ull, e2 = 0ull, e3 = 0ull;
            const float* kpE = Kcur + je * KP;
            const float* QhE = Qe + rh_e * 4 * DIM;
#pragma unroll
            for (int it = 0; it < 4; it++) {
                const int b = (g + it * 8) * 4;   // float offset of 4-d block
                const ulonglong2 k2 = *(const ulonglong2*)&kpE[b];
                const ulonglong2 w2 = *(const ulonglong2*)&wAs[b];
                {
                    const ulonglong2 q2 = *(const ulonglong2*)&QhE[0 * DIM + b];
                    e0 = FMA2(RELU2(ADD2(q2.x, k2.x)), w2.x, e0);
                    e0 = FMA2(RELU2(ADD2(q2.y, k2.y)), w2.y, e0);
                }
                {
                    const ulonglong2 q2 = *(const ulonglong2*)&QhE[1 * DIM + b];
                    e1 = FMA2(RELU2(ADD2(q2.x, k2.x)), w2.x, e1);
                    e1 = FMA2(RELU2(ADD2(q2.y, k2.y)), w2.y, e1);
                }
                {
                    const ulonglong2 q2 = *(const ulonglong2*)&QhE[2 * DIM + b];
                    e2 = FMA2(RELU2(ADD2(q2.x, k2.x)), w2.x, e2);
                    e2 = FMA2(RELU2(ADD2(q2.y, k2.y)), w2.y, e2);
                }
                {
                    const ulonglong2 q2 = *(const ulonglong2*)&QhE[3 * DIM + b];
                    e3 = FMA2(RELU2(ADD2(q2.x, k2.x)), w2.x, e3);
                    e3 = FMA2(RELU2(ADD2(q2.y, k2.y)), w2.y, e3);
                }
            }
            float f0 = HSUM2(e0), f1 = HSUM2(e1), f2 = HSUM2(e2), f3 = HSUM2(e3);
            // reduce-scatter over g (3 shfl rounds: xor4, xor8, xor16)
            const bool hi0 = (g & 1);
            float sA = hi0 ? f0 : f1;
            float sB = hi0 ? f2 : f3;
            const float rA = __shfl_xor_sync(0xffffffffu, sA, 4);
            const float rB = __shfl_xor_sync(0xffffffffu, sB, 4);
            const float u_ = (hi0 ? f1 : f0) + rA;   // row (g&1)
            const float v_ = (hi0 ? f3 : f2) + rB;   // row 2+(g&1)
            const bool hi1 = ((g >> 1) & 1);
            float s2 = hi1 ? u_ : v_;
            const float r2 = __shfl_xor_sync(0xffffffffu, s2, 8);
            const float ep = (hi1 ? v_ : u_) + r2;   // row g&3, partial over g bit2
            const float e_ = ep + __shfl_xor_sync(0xffffffffu, ep, 16);  // full
            const float p_ = exp2f(e_ * LOG2E);      // |e| <~ 3: no max-shift
            if (lane < 16) {   // lanes 16..31 duplicate
                *(float2*)&p16d[je * 16 + 2 * (rh_e * 4 + (g & 3))]
                    = make_float2(p_, p_);
                l_acc += p_;
            }
        }
        __syncthreads();   // p16d ready; phase-e reads of Kcur done

        // issue K(ti+1), V(ti+1) into other buffers — overlaps accumulate
        if (ti + 1 < NTILE) {
            const unsigned kbn = (ti & 1) ? kb0 : kb1;
            const unsigned vbn = (ti & 1) ? vb0 : vb1;
            const float4* Kg = (const float4*)(g_K + (ti + 1) * TJ * DIM);
            const float4* Vg = (const float4*)(g_V + (ti + 1) * TJ * DIM);
#pragma unroll
            for (int it = 0; it < 2; it++) {
                cpa16(kbn + koff[it], &Kg[it * NT + tid]);
                cpa16(vbn + koff[it], &Vg[it * NT + tid]);
            }
            CP_COMMIT();
        }

        // ---- accumulate: d-pair dp, rows rh*4..+3, j-eighth jq
        {
            const float* kpb = Kcur + 2 * dp;
            const float* vpb = Vcur + 2 * dp;
            const float* pp  = p16d + 8 * rh;
#pragma unroll
            for (int jj = 0; jj < 8; jj++) {
                const int j = jq * 8 + jj;
                const ull kv = *(const ull*)&kpb[j * KP];
                const ull vv = *(const ull*)&vpb[j * KP];
                const ulonglong2 pA = *(const ulonglong2*)&pp[j * 16];     // rows 4rh,4rh+1
                const ulonglong2 pB = *(const ulonglong2*)&pp[j * 16 + 4]; // rows 4rh+2,4rh+3
                af0 = FMA2(pA.x, RELU2(ADD2(q0p, kv)), af0);
                av0 = FMA2(pA.x, vv, av0);
                af1 = FMA2(pA.y, RELU2(ADD2(q1p, kv)), af1);
                av1 = FMA2(pA.y, vv, av1);
                af2 = FMA2(pB.x, RELU2(ADD2(q2p, kv)), af2);
                av2 = FMA2(pB.x, vv, av2);
                af3 = FMA2(pB.y, RELU2(ADD2(q3p, kv)), af3);
                av3 = FMA2(pB.y, vv, av3);
            }
        }
    }

    // ================= epilogue =================
    // reduce l_acc over the 4 je-lanes of each g-quad (lanes<16 hold values)
    l_acc += __shfl_xor_sync(0xffffffffu, l_acc, 1);
    l_acc += __shfl_xor_sync(0xffffffffu, l_acc, 2);
    if (lane < 16 && (lane & 3) == 0)
        l_ws[warp * 4 + (lane >> 2)] = l_acc;   // row (rh_e*4 + g&3)
    __syncthreads();                 // main-loop reads done; l_ws published

    // exchange: af in Kb0, av in Vb0 (both dead: final tile used Kb1/Vb1)
    // layout: x[(rh*4 + a)*8 + jq)*64 + dp] as ull, a in [0,4)
    ull* xchF = (ull*)Kb0;           // 2*4*8*64 = 4096 ull = 32KB <= 33KB
    ull* xchV = (ull*)Vb0;
    {
        const int bse = ((rh * 4 + 0) * 8 + jq) * 64 + dp;
        xchF[bse + 0 * 512] = af0;   // row rh*4+a at bse + a*512
        xchF[bse + 1 * 512] = af1;
        xchF[bse + 2 * 512] = af2;
        xchF[bse + 3 * 512] = af3;
        xchV[bse + 0 * 512] = av0;
        xchV[bse + 1 * 512] = av1;
        xchV[bse + 2 * 512] = av2;
        xchV[bse + 3 * 512] = av3;
    }
    __syncthreads();

    // combine over jq, normalize; Rp[k][8] in Kb1, avs[8][128] in Qe
    float* Rp  = Kb1;
    float* avs = Qe;
    {
        const int d = tid & 127, r = tid >> 7;   // one (d, r) per thread
        const int dpc = d >> 1, hc = d & 1;
        const int rhh = r >> 2, ra = r & 3;
        const float* xfF = (const float*)xchF;
        const float* xfV = (const float*)xchV;
        float lr = 0.f;
#pragma unroll
        for (int w = 0; w < 16; w++) lr += l_ws[(rhh * 16 + w) * 4 + ra];
        const float il = 1.f / lr;
        float af = 0.f, av = 0.f;
#pragma unroll
        for (int q = 0; q < 8; q++) {
            const int o = (((rhh * 4 + ra) * 8 + q) * 64 + dpc) * 2 + hc;
            af += xfF[o];
            av += xfV[o];
        }
        Rp[d * 8 + r]    = af * il;
        avs[r * 128 + d] = av * il;
    }
    __syncthreads();

    // GEMM: thread (d, r) computes out[i0+r][d]
    {
        const int d = tid & 127, r = tid >> 7;
        float o = avs[r * 128 + d] + b_Ev[d];
#pragma unroll 8
        for (int k = 0; k < DIM; k++) {
            o += W_Ev[k * DIM + d] * Rp[k * 8 + r];   // LDG coalesced + LDS bcast
        }
        out[(i0 + r) * DIM + d] = o;
    }
}

// ---------------------------------------------------------------------------
extern "C" void kernel_launch(void* const* d_in, const int* in_sizes, int n_in,
                              void* d_out, int out_size)
{
    const float* x    = (const float*)d_in[0];
    const float* W_Q  = (const float*)d_in[1];
    const float* b_Q  = (const float*)d_in[2];
    const float* W_K  = (const float*)d_in[3];
    const float* b_K  = (const float*)d_in[4];
    const float* W_V  = (const float*)d_in[5];
    const float* b_V  = (const float*)d_in[6];
    const float* W_Ev = (const float*)d_in[7];
    const float* b_Ev = (const float*)d_in[8];
    const float* W_A  = (const float*)d_in[9];
    // d_in[10] = b_A: cancels in softmax; sum(alpha)=1 handles b_Ev; unused.
    float* out = (float*)d_out;

    const int smem2 = 36096 * (int)sizeof(float);  // 144384 B -> 1 CTA/SM
    cudaFuncSetAttribute(attn_kernel, cudaFuncAttributeMaxDynamicSharedMemorySize, smem2);

    qkv_kernel<<<NTOK / 8, 384>>>(x, W_Q, b_Q, W_K, b_K, W_V, b_V);
    attn_kernel<<<NTOK / TI, NT, smem2>>>(W_A, W_Ev, b_Ev, out);
}